// round 11
// baseline (speedup 1.0000x reference)
#include <cuda_runtime.h>
#include <cuda_fp16.h>
#include <cstdint>

#define ULL unsigned long long

// ---------------- global scratch (no allocation) ----------------
__device__ float g_ha[512 * 768];
__device__ float g_hb[512 * 768];
__device__ __half g_xh[2][512 * 768];

__device__ __forceinline__ ULL fma2(ULL a, ULL b, ULL c) {
    ULL d;
    asm("fma.rn.f32x2 %0, %1, %2, %3;" : "=l"(d) : "l"(a), "l"(b), "l"(c));
    return d;
}
__device__ __forceinline__ ULL add2(ULL a, ULL b) {
    ULL d;
    asm("add.rn.f32x2 %0, %1, %2;" : "=l"(d) : "l"(a), "l"(b));
    return d;
}
union F2U { ULL u; float2 f; };
union F4U { float4 f; ULL u[2]; float s[4]; uint4 q; };
union H4U { __half2 h2[2]; uint2 q; };

__device__ __forceinline__ uint32_t s2u(const void* p) {
    uint32_t a;
    asm("{ .reg .u64 t; cvta.to.shared.u64 t, %1; cvt.u32.u64 %0, t; }" : "=r"(a) : "l"(p));
    return a;
}
__device__ __forceinline__ void cpa16(const void* smem_dst, const void* gsrc) {
    uint32_t d = s2u(smem_dst);
    asm volatile("cp.async.ca.shared.global [%0], [%1], 16;" :: "r"(d), "l"(gsrc) : "memory");
}
__device__ __forceinline__ void redadd2(float* p, float v0, float v1) {
    asm volatile("red.global.add.v2.f32 [%0], {%1, %2};"
                 :: "l"(p), "f"(v0), "f"(v1) : "memory");
}
#define CP_COMMIT() asm volatile("cp.async.commit_group;" ::: "memory")
#define CP_WAIT2()  asm volatile("cp.async.wait_group 2;" ::: "memory")

#define LDSM4(r, addr)                                                         \
    asm volatile("ldmatrix.sync.aligned.m8n8.x4.shared.b16 {%0,%1,%2,%3}, [%4];" \
                 : "=r"((r)[0]), "=r"((r)[1]), "=r"((r)[2]), "=r"((r)[3])      \
                 : "r"(addr))
#define LDSM4T(r, addr)                                                        \
    asm volatile("ldmatrix.sync.aligned.m8n8.x4.trans.shared.b16 {%0,%1,%2,%3}, [%4];" \
                 : "=r"((r)[0]), "=r"((r)[1]), "=r"((r)[2]), "=r"((r)[3])      \
                 : "r"(addr))
#define MMA16816(c, a, b)                                                      \
    asm volatile("mma.sync.aligned.m16n8k16.row.col.f32.f16.f16.f32 "          \
                 "{%0,%1,%2,%3},{%4,%5,%6,%7},{%8,%9},{%0,%1,%2,%3};"          \
                 : "+f"((c)[0]), "+f"((c)[1]), "+f"((c)[2]), "+f"((c)[3])      \
                 : "r"((a)[0]), "r"((a)[1]), "r"((a)[2]), "r"((a)[3]),         \
                   "r"((b)[0]), "r"((b)[1]))

// ---------------------------------------------------------------------------
// cvt_x: fp32 -> fp16 for X (a,b) only, plus out init to broadcast b2.
// W1 is converted inline by gemm. MLP=4, front-batched loads.
// Units: X 196608, out 32768 = 229376 = 224 blocks x 256 thr x 4.
// ---------------------------------------------------------------------------
__global__ __launch_bounds__(256) void cvt_x_kernel(
    const float* __restrict__ A, const float* __restrict__ Bx,
    const float* __restrict__ b2, float* __restrict__ out)
{
    const int idx = blockIdx.x * 256 + threadIdx.x;      // 0..57343
    float4 v[4];
    __half* dh[4];
    int oidx[4];

#pragma unroll
    for (int j = 0; j < 4; j++) {
        const int u = idx + j * 57344;
        dh[j] = nullptr; oidx[j] = -1;
        if (u < 196608) {
            int z = u / 98304;
            int r = u - z * 98304;
            v[j] = *(const float4*)&((z ? Bx : A)[r * 4]);
            dh[j] = &g_xh[z][r * 4];
        } else {
            oidx[j] = u - 196608;           // 0..32767
        }
    }

#pragma unroll
    for (int j = 0; j < 4; j++) {
        if (dh[j]) {
            H4U h;
            h.h2[0] = __float22half2_rn(make_float2(v[j].x, v[j].y));
            h.h2[1] = __float22half2_rn(make_float2(v[j].z, v[j].w));
            *(uint2*)dh[j] = h.q;
        } else {
            float b0 = b2[0], b1v = b2[1];
            *(float4*)&out[oidx[j] * 4] = make_float4(b0, b1v, b0, b1v);
        }
    }
}

// ---------------------------------------------------------------------------
// gemm: fp16 warp-MMA GEMM with INLINE W conversion.
// D = X@W (+b1 if z==0), fp32 accumulate.
// A (X, fp16): 4-stage cp.async from g_xh.
// B (W, fp32->fp16): LDG.128 fp32 -> F2FP pack -> STS, 2-stage reg pipeline.
// BM=64, BN=64, BK=32 (2 k-steps/chunk), 24 chunks.
// Grid (8 m, 12 n, 2 z) = 192 CTAs, 256 thr (8 warps: 4m x 2n).
// Pads: A rows 40 halfs, B rows 72 halfs (ldmatrix conflict-free).
// ---------------------------------------------------------------------------
__global__ __launch_bounds__(256) void gemm_kernel(
    const float* __restrict__ W1, const float* __restrict__ b1)
{
    const int z  = blockIdx.z;
    const int m0 = blockIdx.x * 64;
    const int n0 = blockIdx.y * 64;

    __shared__ __half As[4][64][40];   // [stage][m][k32 pad40]
    __shared__ __half Bs[2][32][72];   // [buf][k][n64 pad72]

    const int tid  = threadIdx.x;
    const int lane = tid & 31;
    const int wid  = tid >> 5;
    const int wm   = wid & 3;      // m 16-row quadrant
    const int wn   = wid >> 2;     // n 32-col half

    const __half*  __restrict__ xs   = g_xh[z];
    const float*   __restrict__ Wsrc = W1 + z * 768 * 768;

    float acc[4][4];
#pragma unroll
    for (int in = 0; in < 4; in++)
#pragma unroll
        for (int r = 0; r < 4; r++) acc[in][r] = 0.f;

    // ldmatrix lane addressing (chunk-invariant)
    const int arow = (lane & 7) + 8 * ((lane >> 3) & 1);
    const int akh  = ((lane >> 4) & 1) * 8;
    const int bk   = (lane & 7) + 8 * ((lane >> 3) & 1);
    const int bn8  = ((lane >> 4) & 1) * 8;

    // A staging: 256 cpa16 ops (1/thread)
    const int amr = tid >> 2, aq = tid & 3;
    // B staging: 512 float4 units, 2/thread: f = 2*tid+j; k=f>>4, nq=f&15
    auto issueA = [&](int c, int s) {
        const int k0 = c * 32;
        cpa16(&As[s][amr][aq * 8], &xs[(m0 + amr) * 768 + k0 + aq * 8]);
    };
    float4 wr[2];
    auto ldW = [&](int c) {
        const int k0 = c * 32;
#pragma unroll
        for (int j = 0; j < 2; j++) {
            int f = tid * 2 + j;
            int k = f >> 4, nq = f & 15;
            wr[j] = *(const float4*)&Wsrc[(k0 + k) * 768 + n0 + nq * 4];
        }
    };
    auto stW = [&](int buf) {
#pragma unroll
        for (int j = 0; j < 2; j++) {
            int f = tid * 2 + j;
            int k = f >> 4, nq = f & 15;
            H4U h;
            h.h2[0] = __float22half2_rn(make_float2(wr[j].x, wr[j].y));
            h.h2[1] = __float22half2_rn(make_float2(wr[j].z, wr[j].w));
            *(uint2*)&Bs[buf][k][nq * 4] = h.q;
        }
    };

    issueA(0, 0); CP_COMMIT();
    issueA(1, 1); CP_COMMIT();
    issueA(2, 2); CP_COMMIT();
    ldW(0);

    for (int c = 0; c < 24; c++) {
        const int s = c & 3;
        const int bb = c & 1;

        stW(bb);              // W(c) regs -> smem buf
        CP_WAIT2();           // A(c) complete
        __syncthreads();      // A(c)+W(c) visible; prior readers done

        if (c + 3 < 24) issueA(c + 3, (c + 3) & 3);
        CP_COMMIT();
        if (c + 1 < 24) ldW(c + 1);     // prefetch next W into regs

#pragma unroll
        for (int kk = 0; kk < 2; kk++) {
            uint32_t a_[4], b0_[4], b1_[4];
            LDSM4(a_, s2u(&As[s][wm * 16 + arow][kk * 16 + akh]));
            LDSM4T(b0_, s2u(&Bs[bb][kk * 16 + bk][wn * 32 + 0  + bn8]));
            LDSM4T(b1_, s2u(&Bs[bb][kk * 16 + bk][wn * 32 + 16 + bn8]));
            MMA16816(acc[0], a_, &b0_[0]);
            MMA16816(acc[1], a_, &b0_[2]);
            MMA16816(acc[2], a_, &b1_[0]);
            MMA16816(acc[3], a_, &b1_[2]);
        }
    }

    // ---- epilogue ----
    float* __restrict__ outp = z ? g_hb : g_ha;
#pragma unroll
    for (int in = 0; in < 4; in++) {
        const int mA = m0 + wm * 16 + (lane >> 2);
        const int nG = n0 + wn * 32 + in * 8 + 2 * (lane & 3);
        float2 v0 = make_float2(acc[in][0], acc[in][1]);
        float2 v1 = make_float2(acc[in][2], acc[in][3]);
        if (z == 0) {
            float2 bb2 = *(const float2*)&b1[nG];
            v0.x += bb2.x; v0.y += bb2.y;
            v1.x += bb2.x; v1.y += bb2.y;
        }
        *(float2*)&outp[mA * 768 + nG]       = v0;
        *(float2*)&outp[(mA + 8) * 768 + nG] = v1;
    }
}

// ---------------------------------------------------------------------------
// pair_kernel: h-split x4 (27.7 warps/SM); partials accumulated into out via
// red.global.add.v2.f32 (out pre-initialized to b2 by cvt_x_kernel).
// Grid (4 b, 8 s-tiles of 16, 16 = t-tile*4 + hs) = 512 blocks, 256 thr.
// Each block: 192 h = 2 chunks of 96, double-buffered.
// ---------------------------------------------------------------------------
__global__ __launch_bounds__(256) void pair_kernel(
    const float* __restrict__ W2, float* __restrict__ out)
{
    const int b  = blockIdx.x;
    const int s0 = blockIdx.y * 16;
    const int t0 = (blockIdx.z >> 2) * 32;
    const int hbase = (blockIdx.z & 3) * 192;

    __shared__ __align__(16) float4 haS[2][8][48];
    __shared__ ULL hbT[2][48][33];
    __shared__ __align__(16) float4 wsS[2][48];

    const int tid  = threadIdx.x;
    const int w    = tid >> 5;
    const int lane = tid & 31;

    const unsigned e0w = (unsigned)tid / 48u, e0p = (unsigned)tid % 48u;
    const unsigned e1 = (unsigned)tid + 256u;
    const unsigned e1w = e1 / 48u, e1p = e1 % 48u;
    unsigned tq[3], hq[3];
#pragma unroll
    for (int i = 0; i < 3; i++) {
        unsigned q = (unsigned)tid + 256u * i;
        tq[i] = q / 24u; hq[i] = q % 24u;
    }

    ULL a00 = 0ull, a01 = 0ull, a10 = 0ull, a11 = 0ull;
    float2 pa0[2], pa1[2];
    float4 pb[3];
    float4 pw;

    {
        const int h0 = hbase;
        pa0[0] = *(const float2*)&g_ha[(b * 128 + s0 + 2 * e0w) * 768 + h0 + 2 * e0p];
        pa0[1] = *(const float2*)&g_ha[(b * 128 + s0 + 2 * e0w + 1) * 768 + h0 + 2 * e0p];
        if (tid < 128) {
            pa1[0] = *(const float2*)&g_ha[(b * 128 + s0 + 2 * e1w) * 768 + h0 + 2 * e1p];
            pa1[1] = *(const float2*)&g_ha[(b * 128 + s0 + 2 * e1w + 1) * 768 + h0 + 2 * e1p];
        }
#pragma unroll
        for (int i = 0; i < 3; i++)
            pb[i] = *(const float4*)&g_hb[(b * 128 + t0 + tq[i]) * 768 + h0 + hq[i] * 4];
        if (tid < 48) pw = *(const float4*)&W2[(h0 + 2 * tid) * 2];
    }
    {
        haS[0][e0w][e0p] = make_float4(pa0[0].x, pa0[0].y, pa0[1].x, pa0[1].y);
        if (tid < 128)
            haS[0][e1w][e1p] = make_float4(pa1[0].x, pa1[0].y, pa1[1].x, pa1[1].y);
#pragma unroll
        for (int i = 0; i < 3; i++) {
            F2U d0; d0.f.x = pb[i].x; d0.f.y = pb[i].y;
            F2U d1; d1.f.x = pb[i].z; d1.f.y = pb[i].w;
            hbT[0][2 * hq[i] + 0][tq[i]] = d0.u;
            hbT[0][2 * hq[i] + 1][tq[i]] = d1.u;
        }
        if (tid < 48) wsS[0][tid] = make_float4(pw.x, pw.z, pw.y, pw.w);
    }

    for (int c = 0; c < 2; c++) {
        const int buf = c & 1;
        if (c < 1) {
            const int h0 = hbase + 96;
            pa0[0] = *(const float2*)&g_ha[(b * 128 + s0 + 2 * e0w) * 768 + h0 + 2 * e0p];
            pa0[1] = *(const float2*)&g_ha[(b * 128 + s0 + 2 * e0w + 1) * 768 + h0 + 2 * e0p];
            if (tid < 128) {
                pa1[0] = *(const float2*)&g_ha[(b * 128 + s0 + 2 * e1w) * 768 + h0 + 2 * e1p];
                pa1[1] = *(const float2*)&g_ha[(b * 128 + s0 + 2 * e1w + 1) * 768 + h0 + 2 * e1p];
            }
#pragma unroll
            for (int i = 0; i < 3; i++)
                pb[i] = *(const float4*)&g_hb[(b * 128 + t0 + tq[i]) * 768 + h0 + hq[i] * 4];
            if (tid < 48) pw = *(const float4*)&W2[(h0 + 2 * tid) * 2];
        }
        __syncthreads();

#pragma unroll 12
        for (int hp = 0; hp < 48; hp++) {
            F4U av; av.f = haS[buf][w][hp];
            ULL vb = hbT[buf][hp][lane];
            F4U wv; wv.f = wsS[buf][hp];

            F2U x0; x0.u = add2(av.u[0], vb);
            x0.f.x = fmaxf(x0.f.x, 0.f);
            x0.f.y = fmaxf(x0.f.y, 0.f);
            F2U x1; x1.u = add2(av.u[1], vb);
            x1.f.x = fmaxf(x1.f.x, 0.f);
            x1.f.y = fmaxf(x1.f.y, 0.f);

            a00 = fma2(x0.u, wv.u[0], a00);
            a01 = fma2(x0.u, wv.u[1], a01);
            a10 = fma2(x1.u, wv.u[0], a10);
            a11 = fma2(x1.u, wv.u[1], a11);
        }

        if (c < 1) {
            const int nb = buf ^ 1;
            haS[nb][e0w][e0p] = make_float4(pa0[0].x, pa0[0].y, pa0[1].x, pa0[1].y);
            if (tid < 128)
                haS[nb][e1w][e1p] = make_float4(pa1[0].x, pa1[0].y, pa1[1].x, pa1[1].y);
#pragma unroll
            for (int i = 0; i < 3; i++) {
                F2U d0; d0.f.x = pb[i].x; d0.f.y = pb[i].y;
                F2U d1; d1.f.x = pb[i].z; d1.f.y = pb[i].w;
                hbT[nb][2 * hq[i] + 0][tq[i]] = d0.u;
                hbT[nb][2 * hq[i] + 1][tq[i]] = d1.u;
            }
            if (tid < 48) wsS[nb][tid] = make_float4(pw.x, pw.z, pw.y, pw.w);
        }
    }

    F2U r00, r01, r10, r11;
    r00.u = a00; r01.u = a01; r10.u = a10; r11.u = a11;

    const int sa = s0 + 2 * w;
    const int t  = t0 + lane;
    float* pA = &out[((b * 128 + sa)     * 128 + t) * 2];
    float* pB = &out[((b * 128 + sa + 1) * 128 + t) * 2];
    redadd2(pA, r00.f.x + r00.f.y, r01.f.x + r01.f.y);
    redadd2(pB, r10.f.x + r10.f.y, r11.f.x + r11.f.y);
}

// ---------------------------------------------------------------------------
extern "C" void kernel_launch(void* const* d_in, const int* in_sizes, int n_in,
                              void* d_out, int out_size)
{
    const float* a  = (const float*)d_in[0];   // (4,128,768)
    const float* bx = (const float*)d_in[1];   // (4,128,768)
    const float* W1 = (const float*)d_in[2];   // (1536,768)
    const float* b1 = (const float*)d_in[3];   // (768,)
    const float* W2 = (const float*)d_in[4];   // (768,2)
    const float* b2 = (const float*)d_in[5];   // (2,)
    float* out = (float*)d_out;                // (4,128,128,2)

    cvt_x_kernel<<<224, 256>>>(a, bx, b2, out);
    gemm_kernel<<<dim3(8, 12, 2), 256>>>(W1, b1);
    pair_kernel<<<dim3(4, 8, 16), 256>>>(W2, out);
}

// round 12
// speedup vs baseline: 1.6656x; 1.6656x over previous
#include <cuda_runtime.h>
#include <cuda_fp16.h>
#include <cstdint>

#define ULL unsigned long long

// ---------------- global scratch (no allocation) ----------------
__device__ float g_ha[512 * 768];
__device__ float g_hb[512 * 768];
__device__ __half g_xh[2][512 * 768];
__device__ __half g_wh[2][768 * 768];   // [k][n], natural layout

__device__ __forceinline__ ULL fma2(ULL a, ULL b, ULL c) {
    ULL d;
    asm("fma.rn.f32x2 %0, %1, %2, %3;" : "=l"(d) : "l"(a), "l"(b), "l"(c));
    return d;
}
__device__ __forceinline__ ULL add2(ULL a, ULL b) {
    ULL d;
    asm("add.rn.f32x2 %0, %1, %2;" : "=l"(d) : "l"(a), "l"(b));
    return d;
}
union F2U { ULL u; float2 f; };
union F4U { float4 f; ULL u[2]; float s[4]; uint4 q; };
union H4U { __half2 h2[2]; uint2 q; };

__device__ __forceinline__ uint32_t s2u(const void* p) {
    uint32_t a;
    asm("{ .reg .u64 t; cvta.to.shared.u64 t, %1; cvt.u32.u64 %0, t; }" : "=r"(a) : "l"(p));
    return a;
}
__device__ __forceinline__ void cpa16(const void* smem_dst, const void* gsrc) {
    uint32_t d = s2u(smem_dst);
    asm volatile("cp.async.ca.shared.global [%0], [%1], 16;" :: "r"(d), "l"(gsrc) : "memory");
}
__device__ __forceinline__ void redadd2(float* p, float v0, float v1) {
    asm volatile("red.global.add.v2.f32 [%0], {%1, %2};"
                 :: "l"(p), "f"(v0), "f"(v1) : "memory");
}
#define CP_COMMIT() asm volatile("cp.async.commit_group;" ::: "memory")
#define CP_WAIT2()  asm volatile("cp.async.wait_group 2;" ::: "memory")

#define LDSM4(r, addr)                                                         \
    asm volatile("ldmatrix.sync.aligned.m8n8.x4.shared.b16 {%0,%1,%2,%3}, [%4];" \
                 : "=r"((r)[0]), "=r"((r)[1]), "=r"((r)[2]), "=r"((r)[3])      \
                 : "r"(addr))
#define LDSM4T(r, addr)                                                        \
    asm volatile("ldmatrix.sync.aligned.m8n8.x4.trans.shared.b16 {%0,%1,%2,%3}, [%4];" \
                 : "=r"((r)[0]), "=r"((r)[1]), "=r"((r)[2]), "=r"((r)[3])      \
                 : "r"(addr))
#define MMA16816(c, a, b)                                                      \
    asm volatile("mma.sync.aligned.m16n8k16.row.col.f32.f16.f16.f32 "          \
                 "{%0,%1,%2,%3},{%4,%5,%6,%7},{%8,%9},{%0,%1,%2,%3};"          \
                 : "+f"((c)[0]), "+f"((c)[1]), "+f"((c)[2]), "+f"((c)[3])      \
                 : "r"((a)[0]), "r"((a)[1]), "r"((a)[2]), "r"((a)[3]),         \
                   "r"((b)[0]), "r"((b)[1]))

// ---------------------------------------------------------------------------
// cvt: fp32 -> fp16 for X (a,b) and W1, plus out-init to broadcast b2.
// BRANCH-FREE: block ranges do uniform work; each thread streams 2 adjacent
// float4 units (32B load, 16B fp16 store).
//   blocks [0,384):   X  (196608 units)
//   blocks [384,960): W  (294912 units)
//   blocks [960,1024): out-init (32768 units)
// ---------------------------------------------------------------------------
__global__ __launch_bounds__(256) void cvt_kernel(
    const float* __restrict__ A, const float* __restrict__ Bx,
    const float* __restrict__ W1, const float* __restrict__ b2,
    float* __restrict__ out)
{
    const int bid = blockIdx.x;
    const int tid = threadIdx.x;

    if (bid < 384) {
        // X: unit u = 2*(bid*256+tid) + {0,1};  z = u/98304
        const int u0 = (bid * 256 + tid) * 2;
        const int z  = u0 / 98304;
        const int r  = u0 - z * 98304;
        const float* src = (z ? Bx : A) + r * 4;
        float4 v0 = *(const float4*)(src);
        float4 v1 = *(const float4*)(src + 4);
        H4U h0, h1;
        h0.h2[0] = __float22half2_rn(make_float2(v0.x, v0.y));
        h0.h2[1] = __float22half2_rn(make_float2(v0.z, v0.w));
        h1.h2[0] = __float22half2_rn(make_float2(v1.x, v1.y));
        h1.h2[1] = __float22half2_rn(make_float2(v1.z, v1.w));
        uint4 q; q.x = h0.q.x; q.y = h0.q.y; q.z = h1.q.x; q.w = h1.q.y;
        *(uint4*)&g_xh[z][r * 4] = q;
    } else if (bid < 960) {
        // W: unit u = 2*((bid-384)*256+tid) + {0,1};  z = u/147456
        const int u0 = ((bid - 384) * 256 + tid) * 2;
        const int z  = u0 / 147456;
        const int r  = u0 - z * 147456;
        const float* src = W1 + (z * 147456 + r) * 4;
        float4 v0 = *(const float4*)(src);
        float4 v1 = *(const float4*)(src + 4);
        H4U h0, h1;
        h0.h2[0] = __float22half2_rn(make_float2(v0.x, v0.y));
        h0.h2[1] = __float22half2_rn(make_float2(v0.z, v0.w));
        h1.h2[0] = __float22half2_rn(make_float2(v1.x, v1.y));
        h1.h2[1] = __float22half2_rn(make_float2(v1.z, v1.w));
        uint4 q; q.x = h0.q.x; q.y = h0.q.y; q.z = h1.q.x; q.w = h1.q.y;
        *(uint4*)&g_wh[z][r * 4] = q;
    } else {
        // out-init: 2 float4 units per thread
        const int i = ((bid - 960) * 256 + tid) * 2;
        const float b0 = b2[0], b1v = b2[1];
        const float4 r = make_float4(b0, b1v, b0, b1v);
        *(float4*)&out[i * 4]     = r;
        *(float4*)&out[i * 4 + 4] = r;
    }
}

// ---------------------------------------------------------------------------
// gemm: fp16 warp-MMA GEMM (R9 verbatim).  D = X@W (+b1 if z==0), fp32 accum.
// BM=64, BN=64, BK=32 (2 k-steps/chunk), 24 chunks, 4-stage cp.async.
// Grid (8 m, 12 n, 2 z) = 192 CTAs, 256 thr (8 warps: 4m x 2n; 16m x 32n).
// ---------------------------------------------------------------------------
__global__ __launch_bounds__(256) void gemm_kernel(const float* __restrict__ b1)
{
    const int z  = blockIdx.z;
    const int m0 = blockIdx.x * 64;
    const int n0 = blockIdx.y * 64;

    __shared__ __half As[4][64][40];   // [stage][m][k32 pad40]
    __shared__ __half Bs[4][32][72];   // [stage][k][n64 pad72]

    const int tid  = threadIdx.x;
    const int lane = tid & 31;
    const int wid  = tid >> 5;
    const int wm   = wid & 3;      // m 16-row quadrant
    const int wn   = wid >> 2;     // n 32-col half

    const __half* __restrict__ xs = g_xh[z];
    const __half* __restrict__ ws = g_wh[z];

    float acc[4][4];
#pragma unroll
    for (int in = 0; in < 4; in++)
#pragma unroll
        for (int r = 0; r < 4; r++) acc[in][r] = 0.f;

    const int arow = (lane & 7) + 8 * ((lane >> 3) & 1);
    const int akh  = ((lane >> 4) & 1) * 8;
    const int bk   = (lane & 7) + 8 * ((lane >> 3) & 1);
    const int bn8  = ((lane >> 4) & 1) * 8;

    const int amr = tid >> 2, aq = tid & 3;
    const int bkr = tid >> 3, bq = tid & 7;

    auto issue = [&](int c, int s) {
        const int k0 = c * 32;
        cpa16(&As[s][amr][aq * 8], &xs[(m0 + amr) * 768 + k0 + aq * 8]);
        cpa16(&Bs[s][bkr][bq * 8], &ws[(k0 + bkr) * 768 + n0 + bq * 8]);
    };

    issue(0, 0); CP_COMMIT();
    issue(1, 1); CP_COMMIT();
    issue(2, 2); CP_COMMIT();

    for (int c = 0; c < 24; c++) {
        const int s = c & 3;
        CP_WAIT2();
        __syncthreads();

        if (c + 3 < 24) issue(c + 3, (c + 3) & 3);
        CP_COMMIT();

#pragma unroll
        for (int kk = 0; kk < 2; kk++) {
            uint32_t a_[4], b0_[4], b1_[4];
            LDSM4(a_, s2u(&As[s][wm * 16 + arow][kk * 16 + akh]));
            LDSM4T(b0_, s2u(&Bs[s][kk * 16 + bk][wn * 32 + 0  + bn8]));
            LDSM4T(b1_, s2u(&Bs[s][kk * 16 + bk][wn * 32 + 16 + bn8]));
            MMA16816(acc[0], a_, &b0_[0]);
            MMA16816(acc[1], a_, &b0_[2]);
            MMA16816(acc[2], a_, &b1_[0]);
            MMA16816(acc[3], a_, &b1_[2]);
        }
    }

    float* __restrict__ outp = z ? g_hb : g_ha;
#pragma unroll
    for (int in = 0; in < 4; in++) {
        const int mA = m0 + wm * 16 + (lane >> 2);
        const int nG = n0 + wn * 32 + in * 8 + 2 * (lane & 3);
        float2 v0 = make_float2(acc[in][0], acc[in][1]);
        float2 v1 = make_float2(acc[in][2], acc[in][3]);
        if (z == 0) {
            float2 bb = *(const float2*)&b1[nG];
            v0.x += bb.x; v0.y += bb.y;
            v1.x += bb.x; v1.y += bb.y;
        }
        *(float2*)&outp[mA * 768 + nG]       = v0;
        *(float2*)&outp[(mA + 8) * 768 + nG] = v1;
    }
}

// ---------------------------------------------------------------------------
// pair_kernel: h-split x4; partials accumulated into out via
// red.global.add.v2.f32 (out pre-initialized to b2 by cvt_kernel).
// Grid (4 b, 8 s-tiles of 16, 16 = hs*4 + t-tile): hs in HIGH bits so the
// 4 blocks hitting the same output addresses are ~128 blocks apart (no
// co-resident same-address REDG contention).
// Each block: 192 h = 2 chunks of 96, double-buffered.
// ---------------------------------------------------------------------------
__global__ __launch_bounds__(256) void pair_kernel(
    const float* __restrict__ W2, float* __restrict__ out)
{
    const int b  = blockIdx.x;
    const int s0 = blockIdx.y * 16;
    const int t0 = (blockIdx.z & 3) * 32;
    const int hbase = (blockIdx.z >> 2) * 192;

    __shared__ __align__(16) float4 haS[2][8][48];
    __shared__ ULL hbT[2][48][33];
    __shared__ __align__(16) float4 wsS[2][48];

    const int tid  = threadIdx.x;
    const int w    = tid >> 5;
    const int lane = tid & 31;

    const unsigned e0w = (unsigned)tid / 48u, e0p = (unsigned)tid % 48u;
    const unsigned e1 = (unsigned)tid + 256u;
    const unsigned e1w = e1 / 48u, e1p = e1 % 48u;
    unsigned tq[3], hq[3];
#pragma unroll
    for (int i = 0; i < 3; i++) {
        unsigned q = (unsigned)tid + 256u * i;
        tq[i] = q / 24u; hq[i] = q % 24u;
    }

    ULL a00 = 0ull, a01 = 0ull, a10 = 0ull, a11 = 0ull;
    float2 pa0[2], pa1[2];
    float4 pb[3];
    float4 pw;

    {
        const int h0 = hbase;
        pa0[0] = *(const float2*)&g_ha[(b * 128 + s0 + 2 * e0w) * 768 + h0 + 2 * e0p];
        pa0[1] = *(const float2*)&g_ha[(b * 128 + s0 + 2 * e0w + 1) * 768 + h0 + 2 * e0p];
        if (tid < 128) {
            pa1[0] = *(const float2*)&g_ha[(b * 128 + s0 + 2 * e1w) * 768 + h0 + 2 * e1p];
            pa1[1] = *(const float2*)&g_ha[(b * 128 + s0 + 2 * e1w + 1) * 768 + h0 + 2 * e1p];
        }
#pragma unroll
        for (int i = 0; i < 3; i++)
            pb[i] = *(const float4*)&g_hb[(b * 128 + t0 + tq[i]) * 768 + h0 + hq[i] * 4];
        if (tid < 48) pw = *(const float4*)&W2[(h0 + 2 * tid) * 2];
    }
    {
        haS[0][e0w][e0p] = make_float4(pa0[0].x, pa0[0].y, pa0[1].x, pa0[1].y);
        if (tid < 128)
            haS[0][e1w][e1p] = make_float4(pa1[0].x, pa1[0].y, pa1[1].x, pa1[1].y);
#pragma unroll
        for (int i = 0; i < 3; i++) {
            F2U d0; d0.f.x = pb[i].x; d0.f.y = pb[i].y;
            F2U d1; d1.f.x = pb[i].z; d1.f.y = pb[i].w;
            hbT[0][2 * hq[i] + 0][tq[i]] = d0.u;
            hbT[0][2 * hq[i] + 1][tq[i]] = d1.u;
        }
        if (tid < 48) wsS[0][tid] = make_float4(pw.x, pw.z, pw.y, pw.w);
    }

    for (int c = 0; c < 2; c++) {
        const int buf = c & 1;
        if (c < 1) {
            const int h0 = hbase + 96;
            pa0[0] = *(const float2*)&g_ha[(b * 128 + s0 + 2 * e0w) * 768 + h0 + 2 * e0p];
            pa0[1] = *(const float2*)&g_ha[(b * 128 + s0 + 2 * e0w + 1) * 768 + h0 + 2 * e0p];
            if (tid < 128) {
                pa1[0] = *(const float2*)&g_ha[(b * 128 + s0 + 2 * e1w) * 768 + h0 + 2 * e1p];
                pa1[1] = *(const float2*)&g_ha[(b * 128 + s0 + 2 * e1w + 1) * 768 + h0 + 2 * e1p];
            }
#pragma unroll
            for (int i = 0; i < 3; i++)
                pb[i] = *(const float4*)&g_hb[(b * 128 + t0 + tq[i]) * 768 + h0 + hq[i] * 4];
            if (tid < 48) pw = *(const float4*)&W2[(h0 + 2 * tid) * 2];
        }
        __syncthreads();

#pragma unroll 12
        for (int hp = 0; hp < 48; hp++) {
            F4U av; av.f = haS[buf][w][hp];
            ULL vb = hbT[buf][hp][lane];
            F4U wv; wv.f = wsS[buf][hp];

            F2U x0; x0.u = add2(av.u[0], vb);
            x0.f.x = fmaxf(x0.f.x, 0.f);
            x0.f.y = fmaxf(x0.f.y, 0.f);
            F2U x1; x1.u = add2(av.u[1], vb);
            x1.f.x = fmaxf(x1.f.x, 0.f);
            x1.f.y = fmaxf(x1.f.y, 0.f);

            a00 = fma2(x0.u, wv.u[0], a00);
            a01 = fma2(x0.u, wv.u[1], a01);
            a10 = fma2(x1.u, wv.u[0], a10);
            a11 = fma2(x1.u, wv.u[1], a11);
        }

        if (c < 1) {
            const int nb = buf ^ 1;
            haS[nb][e0w][e0p] = make_float4(pa0[0].x, pa0[0].y, pa0[1].x, pa0[1].y);
            if (tid < 128)
                haS[nb][e1w][e1p] = make_float4(pa1[0].x, pa1[0].y, pa1[1].x, pa1[1].y);
#pragma unroll
            for (int i = 0; i < 3; i++) {
                F2U d0; d0.f.x = pb[i].x; d0.f.y = pb[i].y;
                F2U d1; d1.f.x = pb[i].z; d1.f.y = pb[i].w;
                hbT[nb][2 * hq[i] + 0][tq[i]] = d0.u;
                hbT[nb][2 * hq[i] + 1][tq[i]] = d1.u;
            }
            if (tid < 48) wsS[nb][tid] = make_float4(pw.x, pw.z, pw.y, pw.w);
        }
    }

    F2U r00, r01, r10, r11;
    r00.u = a00; r01.u = a01; r10.u = a10; r11.u = a11;

    const int sa = s0 + 2 * w;
    const int t  = t0 + lane;
    float* pA = &out[((b * 128 + sa)     * 128 + t) * 2];
    float* pB = &out[((b * 128 + sa + 1) * 128 + t) * 2];
    redadd2(pA, r00.f.x + r00.f.y, r01.f.x + r01.f.y);
    redadd2(pB, r10.f.x + r10.f.y, r11.f.x + r11.f.y);
}

// ---------------------------------------------------------------------------
extern "C" void kernel_launch(void* const* d_in, const int* in_sizes, int n_in,
                              void* d_out, int out_size)
{
    const float* a  = (const float*)d_in[0];   // (4,128,768)
    const float* bx = (const float*)d_in[1];   // (4,128,768)
    const float* W1 = (const float*)d_in[2];   // (1536,768)
    const float* b1 = (const float*)d_in[3];   // (768,)
    const float* W2 = (const float*)d_in[4];   // (768,2)
    const float* b2 = (const float*)d_in[5];   // (2,)
    float* out = (float*)d_out;                // (4,128,128,2)

    cvt_kernel<<<1024, 256>>>(a, bx, W1, b2, out);
    gemm_kernel<<<dim3(8, 12, 2), 256>>>(b1);
    pair_kernel<<<dim3(4, 8, 16), 256>>>(W2, out);
}